// round 4
// baseline (speedup 1.0000x reference)
#include <cuda_runtime.h>
#include <math.h>
#include <stdint.h>

#define BB 4
#define LL 8192
#define DM 64
#define HH 8
#define DFF 256
#define UU 50
#define ROWS (BB*LL)
#define CHUNK 512
#define NSPLIT 16

__device__ __align__(16) float g_x[ROWS*DM];
__device__ __align__(16) float g_q[ROWS*DM];
__device__ __align__(16) float g_k[ROWS*DM];
__device__ __align__(16) float g_v[ROWS*DM];
__device__ __align__(16) float g_ctx[ROWS*DM];
__device__ __align__(16) float g_y[ROWS*DFF];
__device__ float g_M[BB*HH*LL];
__device__ int   g_top[BB*HH*UU];
__device__ float g_vpart[BB*16*DM];
__device__ float g_vmean[BB*DM];
__device__ float g_part[BB*HH*UU*NSPLIT*10];
__device__ float2 g_div[32];

__global__ void k_div() {
    int i = threadIdx.x;
    double dvd = exp(((double)(-2*i)) * (log(10000.0) / 64.0));
    float hi = (float)dvd;
    g_div[i] = make_float2(hi, (float)(dvd - (double)hi));
}

__global__ void k_embed(const float* __restrict__ xe, const float* __restrict__ ew) {
    int gid = blockIdx.x*256 + threadIdx.x;
    int d = gid & 63, row = gid >> 6;
    int l = row & (LL-1), b = row >> 13;
    const float* xb = xe + b*LL;
    float tok = ew[d*3+0]*xb[(l+LL-1)&(LL-1)] + ew[d*3+1]*xb[l] + ew[d*3+2]*xb[(l+1)&(LL-1)];
    float2 dv = g_div[d >> 1];
    float lf = (float)l;
    float ph = lf * dv.x;
    float perr = fmaf(lf, dv.x, -ph);
    float plo = fmaf(lf, dv.y, perr);
    float kq = rintf(ph * 0.63661977236758134f);
    float r = fmaf(-kq, 1.57079637050628662109375f, ph);
    r = fmaf(kq, 4.37113900018624283e-08f, r);
    r += plo;
    int qd = (((int)kq) + (d & 1)) & 3;
    float sr = sinf(r), cr = cosf(r);
    float pe = (qd == 0) ? sr : (qd == 1) ? cr : (qd == 2) ? -sr : -cr;
    g_x[gid] = tok + pe;
}

__global__ __launch_bounds__(256) void k_qkv(
    const float* __restrict__ Wq, const float* __restrict__ bq,
    const float* __restrict__ Wk, const float* __restrict__ bk,
    const float* __restrict__ Wv, const float* __restrict__ bv)
{
    __shared__ __align__(16) float xT[64*36];
    int row0 = blockIdx.x * 32, tid = threadIdx.x;
    for (int i = tid; i < 2048; i += 256) { int c=i&63, r=i>>6; xT[c*36+r] = g_x[(row0+r)*64+c]; }
    __syncthreads();
    int col = tid & 63, rg = tid >> 6;
    float aq[8], ak[8], av[8];
    #pragma unroll
    for (int j = 0; j < 8; j++) { aq[j]=0.f; ak[j]=0.f; av[j]=0.f; }
    #pragma unroll 4
    for (int kk = 0; kk < 64; kk++) {
        float wq = Wq[kk*64+col], wk = Wk[kk*64+col], wv = Wv[kk*64+col];
        float4 xa = *reinterpret_cast<const float4*>(&xT[kk*36 + rg*8]);
        float4 xb = *reinterpret_cast<const float4*>(&xT[kk*36 + rg*8 + 4]);
        float xs[8] = {xa.x,xa.y,xa.z,xa.w,xb.x,xb.y,xb.z,xb.w};
        #pragma unroll
        for (int j = 0; j < 8; j++) {
            aq[j] = fmaf(xs[j], wq, aq[j]);
            ak[j] = fmaf(xs[j], wk, ak[j]);
            av[j] = fmaf(xs[j], wv, av[j]);
        }
    }
    float b1 = bq[col], b2 = bk[col], b3 = bv[col];
    #pragma unroll
    for (int j = 0; j < 8; j++) {
        int row = row0 + rg*8 + j;
        g_q[row*64+col] = aq[j] + b1;
        g_k[row*64+col] = ak[j] + b2;
        g_v[row*64+col] = av[j] + b3;
    }
}

__global__ __launch_bounds__(256) void k_mscore(const int* __restrict__ idxs)
{
    int wid = blockIdx.x*8 + (threadIdx.x>>5);
    int lane = threadIdx.x & 31;
    int b = wid >> 13, l = wid & (LL-1);
    const int* ib = idxs + l*UU;
    int i1 = ib[lane];
    int i2 = (lane < 18) ? ib[32+lane] : 0;
    int piece = lane & 15;
    float4 qv = reinterpret_cast<const float4*>(g_q + (b*LL + l)*64)[piece];
    float runmax = -INFINITY, runsum = 0.f;
    int rgrp = lane >> 4;
    #pragma unroll 5
    for (int it = 0; it < 25; it++) {
        int r = it*2 + rgrp;
        int idx = (r < 32) ? __shfl_sync(0xffffffffu, i1, r)
                           : __shfl_sync(0xffffffffu, i2, r-32);
        float4 kv = reinterpret_cast<const float4*>(g_k + (b*LL + idx)*64)[piece];
        float dd = qv.x*kv.x;
        dd = fmaf(qv.y, kv.y, dd);
        dd = fmaf(qv.z, kv.z, dd);
        dd = fmaf(qv.w, kv.w, dd);
        dd += __shfl_xor_sync(0xffffffffu, dd, 1);
        runmax = fmaxf(runmax, dd);
        runsum += dd;
    }
    runmax = fmaxf(runmax, __shfl_xor_sync(0xffffffffu, runmax, 16));
    runsum +=              __shfl_xor_sync(0xffffffffu, runsum, 16);
    runmax = fmaxf(runmax, __shfl_xor_sync(0xffffffffu, runmax, 1));
    runsum +=              __shfl_xor_sync(0xffffffffu, runsum, 1);
    if ((lane & 1) == 0 && lane < 16) {
        int h = lane >> 1;
        g_M[(b*HH + h)*LL + l] = runmax - runsum * (1.0f/16384.0f);
    }
}

__global__ __launch_bounds__(256) void k_topk()
{
    __shared__ float sM[8192];
    __shared__ float cval[256];
    __shared__ int   cidx[256];
    __shared__ float wv[8];
    __shared__ int   wi[8];
    __shared__ int   bwin;
    int bh = blockIdx.x, tid = threadIdx.x;
    const float* base = g_M + bh*LL;
    for (int i = tid; i < 8192; i += 256) sM[i] = base[i];
    __syncthreads();
    {
        float lv = -INFINITY; int li = 0, s0 = tid*32;
        #pragma unroll 8
        for (int j = 0; j < 32; j++) { float v = sM[s0+j]; if (v > lv) { lv = v; li = s0+j; } }
        cval[tid] = lv; cidx[tid] = li;
    }
    __syncthreads();
    for (int u = 0; u < UU; u++) {
        float v = cval[tid]; int ix = cidx[tid];
        #pragma unroll
        for (int o = 16; o; o >>= 1) {
            float v2 = __shfl_down_sync(0xffffffffu, v, o);
            int   i2 = __shfl_down_sync(0xffffffffu, ix, o);
            if (v2 > v || (v2 == v && i2 < ix)) { v = v2; ix = i2; }
        }
        if ((tid & 31) == 0) { wv[tid>>5] = v; wi[tid>>5] = ix; }
        __syncthreads();
        if (tid < 32) {
            float v8 = (tid < 8) ? wv[tid] : -INFINITY;
            int   i8 = (tid < 8) ? wi[tid] : 0x7fffffff;
            #pragma unroll
            for (int o = 4; o; o >>= 1) {
                float v2 = __shfl_down_sync(0xffffffffu, v8, o);
                int   i2 = __shfl_down_sync(0xffffffffu, i8, o);
                if (v2 > v8 || (v2 == v8 && i2 < i8)) { v8 = v2; i8 = i2; }
            }
            if (tid == 0) { g_top[bh*UU + u] = i8; bwin = i8; sM[i8] = -INFINITY; }
        }
        __syncthreads();
        if (tid == (bwin >> 5)) {
            float lv = -INFINITY; int li = 0, s0 = tid*32;
            #pragma unroll 8
            for (int j = 0; j < 32; j++) { float vv = sM[s0+j]; if (vv > lv) { lv = vv; li = s0+j; } }
            cval[tid] = lv; cidx[tid] = li;
        }
        __syncthreads();
    }
}

__global__ void k_vpart()
{
    __shared__ float sm[4][64];
    int b = blockIdx.x >> 4, seg = blockIdx.x & 15;
    int d = threadIdx.x & 63, lg = threadIdx.x >> 6;
    const float* base = g_v + (b*LL + seg*512 + lg*128)*64 + d;
    float s = 0.f;
    for (int i = 0; i < 128; i++) s += base[i*64];
    sm[lg][d] = s;
    __syncthreads();
    if (threadIdx.x < 64)
        g_vpart[(b*16 + seg)*64 + threadIdx.x] =
            sm[0][threadIdx.x] + sm[1][threadIdx.x] + sm[2][threadIdx.x] + sm[3][threadIdx.x];
}

__global__ void k_vmerge()
{
    int t = threadIdx.x;
    int b = t >> 6, d = t & 63;
    float s = 0.f;
    for (int i = 0; i < 16; i++) s += g_vpart[(b*16+i)*64 + d];
    g_vmean[t] = s * (1.0f/8192.0f);
}

__global__ void k_ctxfill()
{
    int gid = blockIdx.x*256 + threadIdx.x;
    g_ctx[gid] = g_vmean[((gid >> 19) << 6) | (gid & 63)];
}

__global__ __launch_bounds__(256) void k_attn()
{
    __shared__ float kT[8*520];
    __shared__ float vT[8*520];
    int bh = blockIdx.x >> 4, split = blockIdx.x & 15;
    int b = bh >> 3, h = bh & 7;
    int l0 = split * CHUNK, tid = threadIdx.x;
    for (int i = tid; i < CHUNK*8; i += 256) {
        int j = i >> 3, e = i & 7;
        int g = (b*LL + l0 + j)*64 + h*8 + e;
        kT[e*520 + j] = g_k[g];
        vT[e*520 + j] = g_v[g];
    }
    __syncthreads();
    int w = tid >> 5, lane = tid & 31;
    const float SCALE = 0.35355339059327373f;
    for (int u = w; u < UU; u += 8) {
        int qi = g_top[bh*UU + u];
        const float4* qp = reinterpret_cast<const float4*>(g_q + (b*LL + qi)*64 + h*8);
        float4 qa = qp[0], qb = qp[1];
        float ssum = 0.f;
        float pv[8] = {0,0,0,0,0,0,0,0};
        for (int j = lane; j < CHUNK; j += 32) {
            float s = qa.x*kT[j];
            s = fmaf(qa.y, kT[520+j], s);
            s = fmaf(qa.z, kT[2*520+j], s);
            s = fmaf(qa.w, kT[3*520+j], s);
            s = fmaf(qb.x, kT[4*520+j], s);
            s = fmaf(qb.y, kT[5*520+j], s);
            s = fmaf(qb.z, kT[6*520+j], s);
            s = fmaf(qb.w, kT[7*520+j], s);
            float p = __expf(s * SCALE);
            ssum += p;
            #pragma unroll
            for (int e = 0; e < 8; e++) pv[e] = fmaf(p, vT[e*520+j], pv[e]);
        }
        #pragma unroll
        for (int o = 16; o; o >>= 1) {
            ssum += __shfl_xor_sync(0xffffffffu, ssum, o);
            #pragma unroll
            for (int e = 0; e < 8; e++) pv[e] += __shfl_xor_sync(0xffffffffu, pv[e], o);
        }
        if (lane == 0) {
            float* pp = g_part + ((bh*UU + u)*NSPLIT + split)*10;
            #pragma unroll
            for (int e = 0; e < 8; e++) pp[e] = pv[e];
            pp[8] = ssum;
        }
    }
}

__global__ void k_merge()
{
    int gid = blockIdx.x*256 + threadIdx.x;
    int e = gid & 7, rest = gid >> 3;
    int u = rest % UU, bh = rest / UU;
    int b = bh >> 3, h = bh & 7;
    const float* pp = g_part + ((bh*UU + u)*NSPLIT)*10;
    float pv = 0.f, ss = 0.f;
    for (int s = 0; s < NSPLIT; s++) { pv += pp[s*10 + e]; ss += pp[s*10 + 8]; }
    int qi = g_top[bh*UU + u];
    g_ctx[(b*LL + qi)*64 + h*8 + e] = pv / ss;
}

__device__ __forceinline__ void ln_epilogue(float* out65, int row0, int tid,
    const float* __restrict__ lg, const float* __restrict__ lb)
{
    int w = tid >> 5, lane = tid & 31;
    float gg0 = lg[lane], gg1 = lg[lane+32], bb0 = lb[lane], bb1 = lb[lane+32];
    #pragma unroll
    for (int rr = 0; rr < 4; rr++) {
        int r = w*4 + rr;
        float v0 = out65[r*65 + lane], v1 = out65[r*65 + lane + 32];
        float s = v0 + v1;
        #pragma unroll
        for (int o = 16; o; o >>= 1) s += __shfl_xor_sync(0xffffffffu, s, o);
        float mean = s * (1.0f/64.0f);
        float d0 = v0 - mean, d1 = v1 - mean;
        float s2 = d0*d0 + d1*d1;
        #pragma unroll
        for (int o = 16; o; o >>= 1) s2 += __shfl_xor_sync(0xffffffffu, s2, o);
        float inv = rsqrtf(s2 * (1.0f/64.0f) + 1e-5f);
        int go = (row0 + r)*64;
        g_x[go + lane]      = fmaf(d0 * inv, gg0, bb0);
        g_x[go + lane + 32] = fmaf(d1 * inv, gg1, bb1);
    }
}

__global__ __launch_bounds__(256) void k_wo_ln(
    const float* __restrict__ W, const float* __restrict__ bo,
    const float* __restrict__ lg, const float* __restrict__ lb)
{
    __shared__ __align__(16) float xT[64*36];
    __shared__ float out[32*65];
    int row0 = blockIdx.x * 32, tid = threadIdx.x;
    for (int i = tid; i < 2048; i += 256) { int c=i&63, r=i>>6; xT[c*36+r] = g_ctx[(row0+r)*64+c]; }
    __syncthreads();
    int col = tid & 63, rg = tid >> 6;
    float acc[8];
    #pragma unroll
    for (int j = 0; j < 8; j++) acc[j] = 0.f;
    #pragma unroll 4
    for (int kk = 0; kk < 64; kk++) {
        float wv = W[kk*64+col];
        float4 xa = *reinterpret_cast<const float4*>(&xT[kk*36 + rg*8]);
        float4 xb = *reinterpret_cast<const float4*>(&xT[kk*36 + rg*8 + 4]);
        float xs[8] = {xa.x,xa.y,xa.z,xa.w,xb.x,xb.y,xb.z,xb.w};
        #pragma unroll
        for (int j = 0; j < 8; j++) acc[j] = fmaf(xs[j], wv, acc[j]);
    }
    float bv2 = bo[col];
    #pragma unroll
    for (int j = 0; j < 8; j++) {
        int r = rg*8 + j;
        out[r*65 + col] = acc[j] + bv2 + g_x[(row0 + r)*64 + col];
    }
    __syncthreads();
    ln_epilogue(out, row0, tid, lg, lb);
}

__global__ __launch_bounds__(256) void k_ffn1(
    const float* __restrict__ W, const float* __restrict__ bias)
{
    __shared__ __align__(16) float xT[64*36];
    int row0 = blockIdx.x * 32, tid = threadIdx.x;
    for (int i = tid; i < 2048; i += 256) { int c=i&63, r=i>>6; xT[c*36+r] = g_x[(row0+r)*64+c]; }
    __syncthreads();
    int col = tid & 63, rg = tid >> 6;
    float acc[32];
    #pragma unroll
    for (int i = 0; i < 32; i++) acc[i] = 0.f;
    #pragma unroll 2
    for (int kk = 0; kk < 64; kk++) {
        float w0 = W[kk*256 + col], w1 = W[kk*256 + 64 + col];
        float w2 = W[kk*256 + 128 + col], w3 = W[kk*256 + 192 + col];
        float4 xa = *reinterpret_cast<const float4*>(&xT[kk*36 + rg*8]);
        float4 xb = *reinterpret_cast<const float4*>(&xT[kk*36 + rg*8 + 4]);
        float xs[8] = {xa.x,xa.y,xa.z,xa.w,xb.x,xb.y,xb.z,xb.w};
        #pragma unroll
        for (int j = 0; j < 8; j++) {
            acc[j]    = fmaf(xs[j], w0, acc[j]);
            acc[8+j]  = fmaf(xs[j], w1, acc[8+j]);
            acc[16+j] = fmaf(xs[j], w2, acc[16+j]);
            acc[24+j] = fmaf(xs[j], w3, acc[24+j]);
        }
    }
    float b0 = bias[col], b1 = bias[64+col], b2 = bias[128+col], b3 = bias[192+col];
    #pragma unroll
    for (int j = 0; j < 8; j++) {
        int ro = (row0 + rg*8 + j)*256;
        g_y[ro + col]       = fmaxf(acc[j]    + b0, 0.f);
        g_y[ro + 64 + col]  = fmaxf(acc[8+j]  + b1, 0.f);
        g_y[ro + 128 + col] = fmaxf(acc[16+j] + b2, 0.f);
        g_y[ro + 192 + col] = fmaxf(acc[24+j] + b3, 0.f);
    }
}

__global__ __launch_bounds__(256) void k_ffn2_ln(
    const float* __restrict__ W, const float* __restrict__ bias,
    const float* __restrict__ lg, const float* __restrict__ lb)
{
    __shared__ __align__(16) float xT[64*36];
    __shared__ float out[32*65];
    int row0 = blockIdx.x * 32, tid = threadIdx.x;
    int col = tid & 63, rg = tid >> 6;
    float acc[8];
    #pragma unroll
    for (int j = 0; j < 8; j++) acc[j] = 0.f;
    for (int t = 0; t < 4; t++) {
        __syncthreads();
        for (int i = tid; i < 2048; i += 256) {
            int c = i & 63, r = i >> 6;
            xT[c*36 + r] = g_y[(row0 + r)*256 + t*64 + c];
        }
        __syncthreads();
        #pragma unroll 4
        for (int kk = 0; kk < 64; kk++) {
            float wv = W[(t*64 + kk)*64 + col];
            float4 xa = *reinterpret_cast<const float4*>(&xT[kk*36 + rg*8]);
            float4 xb = *reinterpret_cast<const float4*>(&xT[kk*36 + rg*8 + 4]);
            float xs[8] = {xa.x,xa.y,xa.z,xa.w,xb.x,xb.y,xb.z,xb.w};
            #pragma unroll
            for (int j = 0; j < 8; j++) acc[j] = fmaf(xs[j], wv, acc[j]);
        }
    }
    float bv2 = bias[col];
    #pragma unroll
    for (int j = 0; j < 8; j++) {
        int r = rg*8 + j;
        out[r*65 + col] = acc[j] + bv2 + g_x[(row0 + r)*64 + col];
    }
    __syncthreads();
    ln_epilogue(out, row0, tid, lg, lb);
}

__global__ __launch_bounds__(256) void k_final(
    const float* __restrict__ lg, const float* __restrict__ lb,
    const float* __restrict__ pw, const float* __restrict__ pb,
    float* __restrict__ outp)
{
    int row = blockIdx.x*8 + (threadIdx.x >> 5);
    int lane = threadIdx.x & 31;
    const float* xr = g_x + row*64;
    float v0 = xr[lane], v1 = xr[lane+32];
    float s = v0 + v1;
    #pragma unroll
    for (int o = 16; o; o >>= 1) s += __shfl_xor_sync(0xffffffffu, s, o);
    float mean = s * (1.0f/64.0f);
    float d0 = v0 - mean, d1 = v1 - mean;
    float s2 = d0*d0 + d1*d1;
    #pragma unroll
    for (int o = 16; o; o >>= 1) s2 += __shfl_xor_sync(0xffffffffu, s2, o);
    float inv = rsqrtf(s2 * (1.0f/64.0f) + 1e-5f);
    float xn0 = fmaf(d0 * inv, lg[lane],    lb[lane]);
    float xn1 = fmaf(d1 * inv, lg[lane+32], lb[lane+32]);
    float lgt[5];
    #pragma unroll
    for (int c = 0; c < 5; c++) {
        float t = fmaf(xn0, pw[lane*5 + c], xn1 * pw[(lane+32)*5 + c]);
        #pragma unroll
        for (int o = 16; o; o >>= 1) t += __shfl_xor_sync(0xffffffffu, t, o);
        lgt[c] = t + pb[c];
    }
    float m = lgt[0];
    #pragma unroll
    for (int c = 1; c < 5; c++) m = fmaxf(m, lgt[c]);
    float e[5], se = 0.f;
    #pragma unroll
    for (int c = 0; c < 5; c++) { e[c] = __expf(lgt[c] - m); se += e[c]; }
    float rse = 1.0f / se;
    if (lane == 0) {
        #pragma unroll
        for (int c = 0; c < 5; c++) outp[row*5 + c] = e[c] * rse;
    }
}

extern "C" void kernel_launch(void* const* d_in, const int* in_sizes, int n_in,
                              void* d_out, int out_size)
{
    const float* x_enc   = (const float*)d_in[0];
    const int*   idxs    = (const int*)  d_in[1];
    const float* emb_w   = (const float*)d_in[2];
    const float* Wq      = (const float*)d_in[3];
    const float* bq      = (const float*)d_in[4];
    const float* Wk      = (const float*)d_in[5];
    const float* bk      = (const float*)d_in[6];
    const float* Wv      = (const float*)d_in[7];
    const float* bv      = (const float*)d_in[8];
    const float* Wo      = (const float*)d_in[9];
    const float* bo      = (const float*)d_in[10];
    const float* c1w     = (const float*)d_in[11];
    const float* c1b     = (const float*)d_in[12];
    const float* c2w     = (const float*)d_in[13];
    const float* c2b     = (const float*)d_in[14];
    const float* ln1g    = (const float*)d_in[15];
    const float* ln1b    = (const float*)d_in[16];
    const float* ln2g    = (const float*)d_in[17];
    const float* ln2b    = (const float*)d_in[18];
    const float* lnfg    = (const float*)d_in[19];
    const float* lnfb    = (const float*)d_in[20];
    const float* projw   = (const float*)d_in[21];
    const float* projb   = (const float*)d_in[22];
    float* outp = (float*)d_out;

    k_div<<<1, 32>>>();
    k_embed<<<ROWS*DM/256, 256>>>(x_enc, emb_w);

    for (int i = 0; i < 2; i++) {
        k_qkv<<<ROWS/32, 256>>>(Wq + i*DM*DM, bq + i*DM, Wk + i*DM*DM, bk + i*DM,
                                Wv + i*DM*DM, bv + i*DM);
        k_mscore<<<ROWS/8, 256>>>(idxs + i*LL*UU);
        k_topk<<<BB*HH, 256>>>();
        k_vpart<<<BB*16, 256>>>();
        k_vmerge<<<1, BB*DM>>>();
        k_ctxfill<<<ROWS*DM/256, 256>>>();
        k_attn<<<BB*HH*NSPLIT, 256>>>();
        k_merge<<<BB*HH*UU*8/256, 256>>>();
        k_wo_ln<<<ROWS/32, 256>>>(Wo + i*DM*DM, bo + i*DM, ln1g + i*DM, ln1b + i*DM);
        k_ffn1<<<ROWS/32, 256>>>(c1w + i*DM*DFF, c1b + i*DFF);
        k_ffn2_ln<<<ROWS/32, 256>>>(c2w + i*DFF*DM, c2b + i*DM, ln2g + i*DM, ln2b + i*DM);
    }
    k_final<<<ROWS/8, 256>>>(lnfg, lnfb, projw, projb, outp);
}

// round 5
// speedup vs baseline: 1.1098x; 1.1098x over previous
#include <cuda_runtime.h>
#include <math.h>
#include <stdint.h>

#define BB 4
#define LL 8192
#define DM 64
#define HH 8
#define DFF 256
#define UU 50
#define ROWS (BB*LL)
#define CHUNK 512
#define NSPLIT 16

__device__ __align__(16) float g_x[ROWS*DM];
__device__ __align__(16) float g_q[ROWS*DM];
__device__ __align__(16) float g_k[ROWS*DM];
__device__ __align__(16) float g_v[ROWS*DM];
__device__ __align__(16) float g_ctx[ROWS*DM];
__device__ float g_M[BB*HH*LL];
__device__ int   g_top[BB*HH*UU];
__device__ float g_vpart[BB*16*DM];
__device__ float g_vmean[BB*DM];
__device__ float g_part[BB*HH*UU*NSPLIT*10];
__device__ float2 g_div[32];

__global__ void k_div() {
    int i = threadIdx.x;
    double dvd = exp(((double)(-2*i)) * (log(10000.0) / 64.0));
    float hi = (float)dvd;
    g_div[i] = make_float2(hi, (float)(dvd - (double)hi));
}

__global__ void k_embed(const float* __restrict__ xe, const float* __restrict__ ew) {
    int gid = blockIdx.x*256 + threadIdx.x;
    int d = gid & 63, row = gid >> 6;
    int l = row & (LL-1), b = row >> 13;
    const float* xb = xe + b*LL;
    float tok = ew[d*3+0]*xb[(l+LL-1)&(LL-1)] + ew[d*3+1]*xb[l] + ew[d*3+2]*xb[(l+1)&(LL-1)];
    float2 dv = g_div[d >> 1];
    float lf = (float)l;
    float ph = lf * dv.x;
    float perr = fmaf(lf, dv.x, -ph);
    float plo = fmaf(lf, dv.y, perr);
    float kq = rintf(ph * 0.63661977236758134f);
    float r = fmaf(-kq, 1.57079637050628662109375f, ph);
    r = fmaf(kq, 4.37113900018624283e-08f, r);
    r += plo;
    int qd = (((int)kq) + (d & 1)) & 3;
    float sr = sinf(r), cr = cosf(r);
    float pe = (qd == 0) ? sr : (qd == 1) ? cr : (qd == 2) ? -sr : -cr;
    g_x[gid] = tok + pe;
}

__global__ __launch_bounds__(256) void k_qkv(
    const float* __restrict__ Wq, const float* __restrict__ bq,
    const float* __restrict__ Wk, const float* __restrict__ bk,
    const float* __restrict__ Wv, const float* __restrict__ bv)
{
    __shared__ __align__(16) float xT[64*36];
    int row0 = blockIdx.x * 32, tid = threadIdx.x;
    for (int i = tid; i < 2048; i += 256) { int c=i&63, r=i>>6; xT[c*36+r] = g_x[(row0+r)*64+c]; }
    __syncthreads();
    int col = tid & 63, rg = tid >> 6;
    float aq[8], ak[8], av[8];
    #pragma unroll
    for (int j = 0; j < 8; j++) { aq[j]=0.f; ak[j]=0.f; av[j]=0.f; }
    #pragma unroll 4
    for (int kk = 0; kk < 64; kk++) {
        float wq = Wq[kk*64+col], wk = Wk[kk*64+col], wv = Wv[kk*64+col];
        float4 xa = *reinterpret_cast<const float4*>(&xT[kk*36 + rg*8]);
        float4 xb = *reinterpret_cast<const float4*>(&xT[kk*36 + rg*8 + 4]);
        float xs[8] = {xa.x,xa.y,xa.z,xa.w,xb.x,xb.y,xb.z,xb.w};
        #pragma unroll
        for (int j = 0; j < 8; j++) {
            aq[j] = fmaf(xs[j], wq, aq[j]);
            ak[j] = fmaf(xs[j], wk, ak[j]);
            av[j] = fmaf(xs[j], wv, av[j]);
        }
    }
    float b1 = bq[col], b2 = bk[col], b3 = bv[col];
    #pragma unroll
    for (int j = 0; j < 8; j++) {
        int row = row0 + rg*8 + j;
        g_q[row*64+col] = aq[j] + b1;
        g_k[row*64+col] = ak[j] + b2;
        g_v[row*64+col] = av[j] + b3;
    }
}

__global__ __launch_bounds__(256) void k_mscore(const int* __restrict__ idxs)
{
    int wid = blockIdx.x*8 + (threadIdx.x>>5);
    int lane = threadIdx.x & 31;
    int b = wid >> 13, l = wid & (LL-1);
    const int* ib = idxs + l*UU;
    int i1 = ib[lane];
    int i2 = (lane < 18) ? ib[32+lane] : 0;
    int piece = lane & 15;
    float4 qv = reinterpret_cast<const float4*>(g_q + (b*LL + l)*64)[piece];
    float runmax = -INFINITY, runsum = 0.f;
    int rgrp = lane >> 4;
    #pragma unroll 5
    for (int it = 0; it < 25; it++) {
        int r = it*2 + rgrp;
        int idx = (r < 32) ? __shfl_sync(0xffffffffu, i1, r)
                           : __shfl_sync(0xffffffffu, i2, r-32);
        float4 kv = reinterpret_cast<const float4*>(g_k + (b*LL + idx)*64)[piece];
        float dd = qv.x*kv.x;
        dd = fmaf(qv.y, kv.y, dd);
        dd = fmaf(qv.z, kv.z, dd);
        dd = fmaf(qv.w, kv.w, dd);
        dd += __shfl_xor_sync(0xffffffffu, dd, 1);
        runmax = fmaxf(runmax, dd);
        runsum += dd;
    }
    runmax = fmaxf(runmax, __shfl_xor_sync(0xffffffffu, runmax, 16));
    runsum +=              __shfl_xor_sync(0xffffffffu, runsum, 16);
    runmax = fmaxf(runmax, __shfl_xor_sync(0xffffffffu, runmax, 1));
    runsum +=              __shfl_xor_sync(0xffffffffu, runsum, 1);
    if ((lane & 1) == 0 && lane < 16) {
        int h = lane >> 1;
        g_M[(b*HH + h)*LL + l] = runmax - runsum * (1.0f/16384.0f);
    }
}

__global__ __launch_bounds__(256) void k_topk()
{
    __shared__ float sM[8192];
    __shared__ float cval[256];
    __shared__ int   cidx[256];
    __shared__ float wv[8];
    __shared__ int   wi[8];
    __shared__ int   bwin;
    int bh = blockIdx.x, tid = threadIdx.x;
    const float* base = g_M + bh*LL;
    for (int i = tid; i < 8192; i += 256) sM[i] = base[i];
    __syncthreads();
    {
        float lv = -INFINITY; int li = 0, s0 = tid*32;
        #pragma unroll 8
        for (int j = 0; j < 32; j++) { float v = sM[s0+j]; if (v > lv) { lv = v; li = s0+j; } }
        cval[tid] = lv; cidx[tid] = li;
    }
    __syncthreads();
    for (int u = 0; u < UU; u++) {
        float v = cval[tid]; int ix = cidx[tid];
        #pragma unroll
        for (int o = 16; o; o >>= 1) {
            float v2 = __shfl_down_sync(0xffffffffu, v, o);
            int   i2 = __shfl_down_sync(0xffffffffu, ix, o);
            if (v2 > v || (v2 == v && i2 < ix)) { v = v2; ix = i2; }
        }
        if ((tid & 31) == 0) { wv[tid>>5] = v; wi[tid>>5] = ix; }
        __syncthreads();
        if (tid < 32) {
            float v8 = (tid < 8) ? wv[tid] : -INFINITY;
            int   i8 = (tid < 8) ? wi[tid] : 0x7fffffff;
            #pragma unroll
            for (int o = 4; o; o >>= 1) {
                float v2 = __shfl_down_sync(0xffffffffu, v8, o);
                int   i2 = __shfl_down_sync(0xffffffffu, i8, o);
                if (v2 > v8 || (v2 == v8 && i2 < i8)) { v8 = v2; i8 = i2; }
            }
            if (tid == 0) { g_top[bh*UU + u] = i8; bwin = i8; sM[i8] = -INFINITY; }
        }
        __syncthreads();
        if (tid == (bwin >> 5)) {
            float lv = -INFINITY; int li = 0, s0 = tid*32;
            #pragma unroll 8
            for (int j = 0; j < 32; j++) { float vv = sM[s0+j]; if (vv > lv) { lv = vv; li = s0+j; } }
            cval[tid] = lv; cidx[tid] = li;
        }
        __syncthreads();
    }
}

__global__ void k_vpart()
{
    __shared__ float sm[4][64];
    int b = blockIdx.x >> 4, seg = blockIdx.x & 15;
    int d = threadIdx.x & 63, lg = threadIdx.x >> 6;
    const float* base = g_v + (b*LL + seg*512 + lg*128)*64 + d;
    float s = 0.f;
    for (int i = 0; i < 128; i++) s += base[i*64];
    sm[lg][d] = s;
    __syncthreads();
    if (threadIdx.x < 64)
        g_vpart[(b*16 + seg)*64 + threadIdx.x] =
            sm[0][threadIdx.x] + sm[1][threadIdx.x] + sm[2][threadIdx.x] + sm[3][threadIdx.x];
}

__global__ void k_vmerge()
{
    int t = threadIdx.x;
    int b = t >> 6, d = t & 63;
    float s = 0.f;
    for (int i = 0; i < 16; i++) s += g_vpart[(b*16+i)*64 + d];
    g_vmean[t] = s * (1.0f/8192.0f);
}

__global__ void k_ctxfill()
{
    int gid = blockIdx.x*256 + threadIdx.x;
    g_ctx[gid] = g_vmean[((gid >> 19) << 6) | (gid & 63)];
}

template<int G>
__device__ __forceinline__ void attn_group(
    int u0, int bh, int b, int h, int lane, int split,
    const float* kT, const float* vT)
{
    const float SCALE = 0.35355339059327373f;
    float4 qa[G], qb[G];
    int uu[G]; bool val[G];
    #pragma unroll
    for (int g = 0; g < G; g++) {
        int u = u0 + g*8;
        val[g] = (u < UU);
        uu[g] = val[g] ? u : 0;
        int qi = g_top[bh*UU + uu[g]];
        const float4* qp = reinterpret_cast<const float4*>(g_q + (b*LL + qi)*64 + h*8);
        qa[g] = qp[0]; qb[g] = qp[1];
    }
    float ssum[G];
    float pv[G][8];
    #pragma unroll
    for (int g = 0; g < G; g++) {
        ssum[g] = 0.f;
        #pragma unroll
        for (int e = 0; e < 8; e++) pv[g][e] = 0.f;
    }
    for (int j = lane; j < CHUNK; j += 32) {
        float k0 = kT[j],        k1 = kT[520+j],   k2 = kT[2*520+j], k3 = kT[3*520+j];
        float k4 = kT[4*520+j],  k5 = kT[5*520+j], k6 = kT[6*520+j], k7 = kT[7*520+j];
        float v0 = vT[j],        v1 = vT[520+j],   v2 = vT[2*520+j], v3 = vT[3*520+j];
        float v4 = vT[4*520+j],  v5 = vT[5*520+j], v6 = vT[6*520+j], v7 = vT[7*520+j];
        #pragma unroll
        for (int g = 0; g < G; g++) {
            float s = qa[g].x*k0;
            s = fmaf(qa[g].y, k1, s);
            s = fmaf(qa[g].z, k2, s);
            s = fmaf(qa[g].w, k3, s);
            s = fmaf(qb[g].x, k4, s);
            s = fmaf(qb[g].y, k5, s);
            s = fmaf(qb[g].z, k6, s);
            s = fmaf(qb[g].w, k7, s);
            float p = __expf(s * SCALE);
            ssum[g] += p;
            pv[g][0] = fmaf(p, v0, pv[g][0]);
            pv[g][1] = fmaf(p, v1, pv[g][1]);
            pv[g][2] = fmaf(p, v2, pv[g][2]);
            pv[g][3] = fmaf(p, v3, pv[g][3]);
            pv[g][4] = fmaf(p, v4, pv[g][4]);
            pv[g][5] = fmaf(p, v5, pv[g][5]);
            pv[g][6] = fmaf(p, v6, pv[g][6]);
            pv[g][7] = fmaf(p, v7, pv[g][7]);
        }
    }
    #pragma unroll
    for (int g = 0; g < G; g++) {
        #pragma unroll
        for (int o = 16; o; o >>= 1) {
            ssum[g] += __shfl_xor_sync(0xffffffffu, ssum[g], o);
            #pragma unroll
            for (int e = 0; e < 8; e++) pv[g][e] += __shfl_xor_sync(0xffffffffu, pv[g][e], o);
        }
        if (lane == 0 && val[g]) {
            float* pp = g_part + ((bh*UU + uu[g])*NSPLIT + split)*10;
            #pragma unroll
            for (int e = 0; e < 8; e++) pp[e] = pv[g][e];
            pp[8] = ssum[g];
        }
    }
}

__global__ __launch_bounds__(256) void k_attn()
{
    __shared__ float kT[8*520];
    __shared__ float vT[8*520];
    int bh = blockIdx.x >> 4, split = blockIdx.x & 15;
    int b = bh >> 3, h = bh & 7;
    int l0 = split * CHUNK, tid = threadIdx.x;
    for (int i = tid; i < CHUNK*8; i += 256) {
        int j = i >> 3, e = i & 7;
        int g = (b*LL + l0 + j)*64 + h*8 + e;
        kT[e*520 + j] = g_k[g];
        vT[e*520 + j] = g_v[g];
    }
    __syncthreads();
    int w = tid >> 5, lane = tid & 31;
    attn_group<4>(w,      bh, b, h, lane, split, kT, vT);   // u = w, w+8, w+16, w+24
    attn_group<3>(w + 32, bh, b, h, lane, split, kT, vT);   // u = w+32, w+40, w+48
}

__global__ void k_merge()
{
    int gid = blockIdx.x*256 + threadIdx.x;
    int e = gid & 7, rest = gid >> 3;
    int u = rest % UU, bh = rest / UU;
    int b = bh >> 3, h = bh & 7;
    const float* pp = g_part + ((bh*UU + u)*NSPLIT)*10;
    float pv = 0.f, ss = 0.f;
    for (int s = 0; s < NSPLIT; s++) { pv += pp[s*10 + e]; ss += pp[s*10 + 8]; }
    int qi = g_top[bh*UU + u];
    g_ctx[(b*LL + qi)*64 + h*8 + e] = pv / ss;
}

__device__ __forceinline__ void ln_epilogue(float* out65, int row0, int tid,
    const float* __restrict__ lg, const float* __restrict__ lb)
{
    int w = tid >> 5, lane = tid & 31;
    float gg0 = lg[lane], gg1 = lg[lane+32], bb0 = lb[lane], bb1 = lb[lane+32];
    #pragma unroll
    for (int rr = 0; rr < 4; rr++) {
        int r = w*4 + rr;
        float v0 = out65[r*65 + lane], v1 = out65[r*65 + lane + 32];
        float s = v0 + v1;
        #pragma unroll
        for (int o = 16; o; o >>= 1) s += __shfl_xor_sync(0xffffffffu, s, o);
        float mean = s * (1.0f/64.0f);
        float d0 = v0 - mean, d1 = v1 - mean;
        float s2 = d0*d0 + d1*d1;
        #pragma unroll
        for (int o = 16; o; o >>= 1) s2 += __shfl_xor_sync(0xffffffffu, s2, o);
        float inv = rsqrtf(s2 * (1.0f/64.0f) + 1e-5f);
        int go = (row0 + r)*64;
        g_x[go + lane]      = fmaf(d0 * inv, gg0, bb0);
        g_x[go + lane + 32] = fmaf(d1 * inv, gg1, bb1);
    }
}

__global__ __launch_bounds__(256) void k_wo_ln(
    const float* __restrict__ W, const float* __restrict__ bo,
    const float* __restrict__ lg, const float* __restrict__ lb)
{
    __shared__ __align__(16) float xT[64*36];
    __shared__ float out[32*65];
    int row0 = blockIdx.x * 32, tid = threadIdx.x;
    for (int i = tid; i < 2048; i += 256) { int c=i&63, r=i>>6; xT[c*36+r] = g_ctx[(row0+r)*64+c]; }
    __syncthreads();
    int col = tid & 63, rg = tid >> 6;
    float acc[8];
    #pragma unroll
    for (int j = 0; j < 8; j++) acc[j] = 0.f;
    #pragma unroll 4
    for (int kk = 0; kk < 64; kk++) {
        float wv = W[kk*64+col];
        float4 xa = *reinterpret_cast<const float4*>(&xT[kk*36 + rg*8]);
        float4 xb = *reinterpret_cast<const float4*>(&xT[kk*36 + rg*8 + 4]);
        float xs[8] = {xa.x,xa.y,xa.z,xa.w,xb.x,xb.y,xb.z,xb.w};
        #pragma unroll
        for (int j = 0; j < 8; j++) acc[j] = fmaf(xs[j], wv, acc[j]);
    }
    float bv2 = bo[col];
    #pragma unroll
    for (int j = 0; j < 8; j++) {
        int r = rg*8 + j;
        out[r*65 + col] = acc[j] + bv2 + g_x[(row0 + r)*64 + col];
    }
    __syncthreads();
    ln_epilogue(out, row0, tid, lg, lb);
}

// Fused FFN: y = relu(x@W1+b1) kept in smem (transposed), then x = LN(x + y@W2 + b2)
__global__ __launch_bounds__(256) void k_ffn(
    const float* __restrict__ W1, const float* __restrict__ b1,
    const float* __restrict__ W2, const float* __restrict__ b2,
    const float* __restrict__ lg, const float* __restrict__ lb)
{
    __shared__ __align__(16) float yT[256*36];   // 36864 B
    __shared__ __align__(16) float xTo[64*36];   // xT in phase1; reused as out[32*65] after
    int row0 = blockIdx.x * 32, tid = threadIdx.x;
    for (int i = tid; i < 2048; i += 256) { int c=i&63, r=i>>6; xTo[c*36+r] = g_x[(row0+r)*64+c]; }
    __syncthreads();
    int col = tid & 63, rg = tid >> 6;
    float acc[32];
    #pragma unroll
    for (int i = 0; i < 32; i++) acc[i] = 0.f;
    #pragma unroll 2
    for (int kk = 0; kk < 64; kk++) {
        float w0 = W1[kk*256 + col], w1 = W1[kk*256 + 64 + col];
        float w2 = W1[kk*256 + 128 + col], w3 = W1[kk*256 + 192 + col];
        float4 xa = *reinterpret_cast<const float4*>(&xTo[kk*36 + rg*8]);
        float4 xb = *reinterpret_cast<const float4*>(&xTo[kk*36 + rg*8 + 4]);
        float xs[8] = {xa.x,xa.y,xa.z,xa.w,xb.x,xb.y,xb.z,xb.w};
        #pragma unroll
        for (int j = 0; j < 8; j++) {
            acc[j]    = fmaf(xs[j], w0, acc[j]);
            acc[8+j]  = fmaf(xs[j], w1, acc[8+j]);
            acc[16+j] = fmaf(xs[j], w2, acc[16+j]);
            acc[24+j] = fmaf(xs[j], w3, acc[24+j]);
        }
    }
    __syncthreads();   // all xTo reads complete (xTo reused for 'out' below)
    #pragma unroll
    for (int t = 0; t < 4; t++) {
        float bb = b1[t*64 + col];
        float4 f0, f1;
        f0.x = fmaxf(acc[t*8+0] + bb, 0.f);
        f0.y = fmaxf(acc[t*8+1] + bb, 0.f);
        f0.z = fmaxf(acc[t*8+2] + bb, 0.f);
        f0.w = fmaxf(acc[t*8+3] + bb, 0.f);
        f1.x = fmaxf(acc[t*8+4] + bb, 0.f);
        f1.y = fmaxf(acc[t*8+5] + bb, 0.f);
        f1.z = fmaxf(acc[t*8+6] + bb, 0.f);
        f1.w = fmaxf(acc[t*8+7] + bb, 0.f);
        *reinterpret_cast<float4*>(&yT[(t*64+col)*36 + rg*8])     = f0;
        *reinterpret_cast<float4*>(&yT[(t*64+col)*36 + rg*8 + 4]) = f1;
    }
    __syncthreads();
    float a2[8];
    #pragma unroll
    for (int j = 0; j < 8; j++) a2[j] = 0.f;
    #pragma unroll 2
    for (int kk = 0; kk < 256; kk++) {
        float wv = W2[kk*64 + col];
        float4 ya = *reinterpret_cast<const float4*>(&yT[kk*36 + rg*8]);
        float4 yb = *reinterpret_cast<const float4*>(&yT[kk*36 + rg*8 + 4]);
        a2[0] = fmaf(ya.x, wv, a2[0]);
        a2[1] = fmaf(ya.y, wv, a2[1]);
        a2[2] = fmaf(ya.z, wv, a2[2]);
        a2[3] = fmaf(ya.w, wv, a2[3]);
        a2[4] = fmaf(yb.x, wv, a2[4]);
        a2[5] = fmaf(yb.y, wv, a2[5]);
        a2[6] = fmaf(yb.z, wv, a2[6]);
        a2[7] = fmaf(yb.w, wv, a2[7]);
    }
    float bv2 = b2[col];
    float* out = xTo;   // reuse (32*65 = 2080 <= 2304 floats)
    #pragma unroll
    for (int j = 0; j < 8; j++) {
        int r = rg*8 + j;
        out[r*65 + col] = a2[j] + bv2 + g_x[(row0 + r)*64 + col];
    }
    __syncthreads();
    ln_epilogue(out, row0, tid, lg, lb);
}

__global__ __launch_bounds__(256) void k_final(
    const float* __restrict__ lg, const float* __restrict__ lb,
    const float* __restrict__ pw, const float* __restrict__ pb,
    float* __restrict__ outp)
{
    int row = blockIdx.x*8 + (threadIdx.x >> 5);
    int lane = threadIdx.x & 31;
    const float* xr = g_x + row*64;
    float v0 = xr[lane], v1 = xr[lane+32];
    float s = v0 + v1;
    #pragma unroll
    for (int o = 16; o; o >>= 1) s += __shfl_xor_sync(0xffffffffu, s, o);
    float mean = s * (1.0f/64.0f);
    float d0 = v0 - mean, d1 = v1 - mean;
    float s2 = d0*d0 + d1*d1;
    #pragma unroll
    for (int o = 16; o; o >>= 1) s2 += __shfl_xor_sync(0xffffffffu, s2, o);
    float inv = rsqrtf(s2 * (1.0f/64.0f) + 1e-5f);
    float xn0 = fmaf(d0 * inv, lg[lane],    lb[lane]);
    float xn1 = fmaf(d1 * inv, lg[lane+32], lb[lane+32]);
    float lgt[5];
    #pragma unroll
    for (int c = 0; c < 5; c++) {
        float t = fmaf(xn0, pw[lane*5 + c], xn1 * pw[(lane+32)*5 + c]);
        #pragma unroll
        for (int o = 16; o; o >>= 1) t += __shfl_xor_sync(0xffffffffu, t, o);
        lgt[c] = t + pb[c];
    }
    float m = lgt[0];
    #pragma unroll
    for (int c = 1; c < 5; c++) m = fmaxf(m, lgt[c]);
    float e[5], se = 0.f;
    #pragma unroll
    for (int c = 0; c < 5; c++) { e[c] = __expf(lgt[c] - m); se += e[c]; }
    float rse = 1.0f / se;
    if (lane == 0) {
        #pragma unroll
        for (int c = 0; c < 5; c++) outp[row*5 + c] = e[c] * rse;
    }
}

extern "C" void kernel_launch(void* const* d_in, const int* in_sizes, int n_in,
                              void* d_out, int out_size)
{
    const float* x_enc   = (const float*)d_in[0];
    const int*   idxs    = (const int*)  d_in[1];
    const float* emb_w   = (const float*)d_in[2];
    const float* Wq      = (const float*)d_in[3];
    const float* bq      = (const float*)d_in[4];
    const float* Wk      = (const float*)d_in[5];
    const float* bk      = (const float*)d_in[6];
    const float* Wv      = (const float*)d_in[7];
    const float* bv      = (const float*)d_in[8];
    const float* Wo      = (const float*)d_in[9];
    const float* bo      = (const float*)d_in[10];
    const float* c1w     = (const float*)d_in[11];
    const float* c1b     = (const float*)d_in[12];
    const float* c2w     = (const float*)d_in[13];
    const float* c2b     = (const float*)d_in[14];
    const float* ln1g    = (const float*)d_in[15];
    const float* ln1b    = (const float*)d_in[16];
    const float* ln2g    = (const float*)d_in[17];
    const float* ln2b    = (const float*)d_in[18];
    const float* lnfg    = (const float*)d_in[19];
    const float* lnfb    = (const float*)d_in[20];
    const float* projw   = (const float*)d_in[21];
    const float* projb   = (const float*)d_in[22];
    float* outp = (float*)d_out;

    k_div<<<1, 32>>>();
    k_embed<<<ROWS*DM/256, 256>>>(x_enc, emb_w);

    for (int i = 0; i < 2; i++) {
        k_qkv<<<ROWS/32, 256>>>(Wq + i*DM*DM, bq + i*DM, Wk + i*DM*DM, bk + i*DM,
                                Wv + i*DM*DM, bv + i*DM);
        k_mscore<<<ROWS/8, 256>>>(idxs + i*LL*UU);
        k_topk<<<BB*HH, 256>>>();
        k_vpart<<<BB*16, 256>>>();
        k_vmerge<<<1, BB*DM>>>();
        k_ctxfill<<<ROWS*DM/256, 256>>>();
        k_attn<<<BB*HH*NSPLIT, 256>>>();
        k_merge<<<BB*HH*UU*8/256, 256>>>();
        k_wo_ln<<<ROWS/32, 256>>>(Wo + i*DM*DM, bo + i*DM, ln1g + i*DM, ln1b + i*DM);
        k_ffn<<<ROWS/32, 256>>>(c1w + i*DM*DFF, c1b + i*DFF, c2w + i*DFF*DM, c2b + i*DM,
                                ln2g + i*DM, ln2b + i*DM);
    }
    k_final<<<ROWS/8, 256>>>(lnfg, lnfb, projw, projb, outp);
}

// round 6
// speedup vs baseline: 1.1817x; 1.0648x over previous
#include <cuda_runtime.h>
#include <math.h>
#include <stdint.h>

#define BB 4
#define LL 8192
#define DM 64
#define HH 8
#define DFF 256
#define UU 50
#define ROWS (BB*LL)
#define CHUNK 512
#define NSPLIT 16

typedef unsigned long long u64;

__device__ __align__(16) float g_x[ROWS*DM];
__device__ __align__(16) float g_q[ROWS*DM];
__device__ __align__(16) float g_k[ROWS*DM];
__device__ __align__(16) float g_v[ROWS*DM];
__device__ __align__(16) float g_ctx[ROWS*DM];
__device__ float g_M[BB*HH*LL];
__device__ int   g_top[BB*HH*UU];
__device__ float g_vpart[BB*16*DM];
__device__ float g_vmean[BB*DM];
__device__ float g_part[BB*HH*UU*NSPLIT*10];
__device__ float2 g_div[32];

// ---- packed fp32x2 helpers (bit-exact: each half is an IEEE fp32 FMA) ----
__device__ __forceinline__ u64 pk2(float lo, float hi) {
    u64 r;
    asm("mov.b64 %0, {%1, %2};" : "=l"(r) : "r"(__float_as_uint(lo)), "r"(__float_as_uint(hi)));
    return r;
}
__device__ __forceinline__ void upk2(u64 v, float &lo, float &hi) {
    unsigned a, b;
    asm("mov.b64 {%0, %1}, %2;" : "=r"(a), "=r"(b) : "l"(v));
    lo = __uint_as_float(a); hi = __uint_as_float(b);
}
__device__ __forceinline__ void fma2(u64 &d, u64 a, u64 b) {
    asm("fma.rn.f32x2 %0, %1, %2, %0;" : "+l"(d) : "l"(a), "l"(b));
}

__global__ void k_div() {
    int i = threadIdx.x;
    double dvd = exp(((double)(-2*i)) * (log(10000.0) / 64.0));
    float hi = (float)dvd;
    g_div[i] = make_float2(hi, (float)(dvd - (double)hi));
}

__global__ void k_embed(const float* __restrict__ xe, const float* __restrict__ ew) {
    int gid = blockIdx.x*256 + threadIdx.x;
    int d = gid & 63, row = gid >> 6;
    int l = row & (LL-1), b = row >> 13;
    const float* xb = xe + b*LL;
    float tok = ew[d*3+0]*xb[(l+LL-1)&(LL-1)] + ew[d*3+1]*xb[l] + ew[d*3+2]*xb[(l+1)&(LL-1)];
    float2 dv = g_div[d >> 1];
    float lf = (float)l;
    float ph = lf * dv.x;
    float perr = fmaf(lf, dv.x, -ph);
    float plo = fmaf(lf, dv.y, perr);
    float kq = rintf(ph * 0.63661977236758134f);
    float r = fmaf(-kq, 1.57079637050628662109375f, ph);
    r = fmaf(kq, 4.37113900018624283e-08f, r);
    r += plo;
    int qd = (((int)kq) + (d & 1)) & 3;
    float sr = sinf(r), cr = cosf(r);
    float pe = (qd == 0) ? sr : (qd == 1) ? cr : (qd == 2) ? -sr : -cr;
    g_x[gid] = tok + pe;
}

__global__ __launch_bounds__(256) void k_qkv(
    const float* __restrict__ Wq, const float* __restrict__ bq,
    const float* __restrict__ Wk, const float* __restrict__ bk,
    const float* __restrict__ Wv, const float* __restrict__ bv)
{
    __shared__ __align__(16) float xT[64*36];
    int row0 = blockIdx.x * 32, tid = threadIdx.x;
    for (int i = tid; i < 2048; i += 256) { int c=i&63, r=i>>6; xT[c*36+r] = g_x[(row0+r)*64+c]; }
    __syncthreads();
    int col = tid & 63, rg = tid >> 6;
    u64 aq2[4], ak2[4], av2[4];
    #pragma unroll
    for (int p = 0; p < 4; p++) { aq2[p]=0ull; ak2[p]=0ull; av2[p]=0ull; }
    #pragma unroll 4
    for (int kk = 0; kk < 64; kk++) {
        u64 wq2 = pk2(Wq[kk*64+col], Wq[kk*64+col]);
        u64 wk2 = pk2(Wk[kk*64+col], Wk[kk*64+col]);
        u64 wv2 = pk2(Wv[kk*64+col], Wv[kk*64+col]);
        const u64* xp = reinterpret_cast<const u64*>(&xT[kk*36 + rg*8]);
        #pragma unroll
        for (int p = 0; p < 4; p++) {
            u64 xv = xp[p];
            fma2(aq2[p], xv, wq2);
            fma2(ak2[p], xv, wk2);
            fma2(av2[p], xv, wv2);
        }
    }
    float b1 = bq[col], b2 = bk[col], b3 = bv[col];
    #pragma unroll
    for (int p = 0; p < 4; p++) {
        float q0,q1,k0,k1,v0,v1;
        upk2(aq2[p], q0, q1); upk2(ak2[p], k0, k1); upk2(av2[p], v0, v1);
        int row = row0 + rg*8 + 2*p;
        g_q[row*64+col] = q0 + b1;       g_q[(row+1)*64+col] = q1 + b1;
        g_k[row*64+col] = k0 + b2;       g_k[(row+1)*64+col] = k1 + b2;
        g_v[row*64+col] = v0 + b3;       g_v[(row+1)*64+col] = v1 + b3;
    }
}

__global__ __launch_bounds__(256) void k_mscore(const int* __restrict__ idxs)
{
    int wid = blockIdx.x*8 + (threadIdx.x>>5);
    int lane = threadIdx.x & 31;
    int b = wid >> 13, l = wid & (LL-1);
    const int* ib = idxs + l*UU;
    int i1 = ib[lane];
    int i2 = (lane < 18) ? ib[32+lane] : 0;
    int piece = lane & 15;
    float4 qv = reinterpret_cast<const float4*>(g_q + (b*LL + l)*64)[piece];
    float runmax = -INFINITY, runsum = 0.f;
    int rgrp = lane >> 4;
    #pragma unroll 5
    for (int it = 0; it < 25; it++) {
        int r = it*2 + rgrp;
        int idx = (r < 32) ? __shfl_sync(0xffffffffu, i1, r)
                           : __shfl_sync(0xffffffffu, i2, r-32);
        float4 kv = reinterpret_cast<const float4*>(g_k + (b*LL + idx)*64)[piece];
        float dd = qv.x*kv.x;
        dd = fmaf(qv.y, kv.y, dd);
        dd = fmaf(qv.z, kv.z, dd);
        dd = fmaf(qv.w, kv.w, dd);
        dd += __shfl_xor_sync(0xffffffffu, dd, 1);
        runmax = fmaxf(runmax, dd);
        runsum += dd;
    }
    runmax = fmaxf(runmax, __shfl_xor_sync(0xffffffffu, runmax, 16));
    runsum +=              __shfl_xor_sync(0xffffffffu, runsum, 16);
    runmax = fmaxf(runmax, __shfl_xor_sync(0xffffffffu, runmax, 1));
    runsum +=              __shfl_xor_sync(0xffffffffu, runsum, 1);
    if ((lane & 1) == 0 && lane < 16) {
        int h = lane >> 1;
        g_M[(b*HH + h)*LL + l] = runmax - runsum * (1.0f/16384.0f);
    }
}

__global__ __launch_bounds__(256) void k_topk()
{
    __shared__ float sM[8192];
    __shared__ float cval[256];
    __shared__ int   cidx[256];
    __shared__ float wv[8];
    __shared__ int   wi[8];
    __shared__ int   bwin;
    int bh = blockIdx.x, tid = threadIdx.x;
    const float* base = g_M + bh*LL;
    for (int i = tid; i < 8192; i += 256) sM[i] = base[i];
    __syncthreads();
    {
        float lv = -INFINITY; int li = 0, s0 = tid*32;
        #pragma unroll 8
        for (int j = 0; j < 32; j++) { float v = sM[s0+j]; if (v > lv) { lv = v; li = s0+j; } }
        cval[tid] = lv; cidx[tid] = li;
    }
    __syncthreads();
    for (int u = 0; u < UU; u++) {
        float v = cval[tid]; int ix = cidx[tid];
        #pragma unroll
        for (int o = 16; o; o >>= 1) {
            float v2 = __shfl_down_sync(0xffffffffu, v, o);
            int   i2 = __shfl_down_sync(0xffffffffu, ix, o);
            if (v2 > v || (v2 == v && i2 < ix)) { v = v2; ix = i2; }
        }
        if ((tid & 31) == 0) { wv[tid>>5] = v; wi[tid>>5] = ix; }
        __syncthreads();
        if (tid < 32) {
            float v8 = (tid < 8) ? wv[tid] : -INFINITY;
            int   i8 = (tid < 8) ? wi[tid] : 0x7fffffff;
            #pragma unroll
            for (int o = 4; o; o >>= 1) {
                float v2 = __shfl_down_sync(0xffffffffu, v8, o);
                int   i2 = __shfl_down_sync(0xffffffffu, i8, o);
                if (v2 > v8 || (v2 == v8 && i2 < i8)) { v8 = v2; i8 = i2; }
            }
            if (tid == 0) { g_top[bh*UU + u] = i8; bwin = i8; sM[i8] = -INFINITY; }
        }
        __syncthreads();
        if (tid == (bwin >> 5)) {
            float lv = -INFINITY; int li = 0, s0 = tid*32;
            #pragma unroll 8
            for (int j = 0; j < 32; j++) { float vv = sM[s0+j]; if (vv > lv) { lv = vv; li = s0+j; } }
            cval[tid] = lv; cidx[tid] = li;
        }
        __syncthreads();
    }
}

__global__ void k_vpart()
{
    __shared__ float sm[4][64];
    int b = blockIdx.x >> 4, seg = blockIdx.x & 15;
    int d = threadIdx.x & 63, lg = threadIdx.x >> 6;
    const float* base = g_v + (b*LL + seg*512 + lg*128)*64 + d;
    float s = 0.f;
    for (int i = 0; i < 128; i++) s += base[i*64];
    sm[lg][d] = s;
    __syncthreads();
    if (threadIdx.x < 64)
        g_vpart[(b*16 + seg)*64 + threadIdx.x] =
            sm[0][threadIdx.x] + sm[1][threadIdx.x] + sm[2][threadIdx.x] + sm[3][threadIdx.x];
}

__global__ void k_vmerge()
{
    int t = threadIdx.x;
    int b = t >> 6, d = t & 63;
    float s = 0.f;
    for (int i = 0; i < 16; i++) s += g_vpart[(b*16+i)*64 + d];
    g_vmean[t] = s * (1.0f/8192.0f);
}

__global__ void k_ctxfill()
{
    int gid = blockIdx.x*256 + threadIdx.x;
    g_ctx[gid] = g_vmean[((gid >> 19) << 6) | (gid & 63)];
}

template<int G>
__device__ __forceinline__ void attn_group(
    int u0, int bh, int b, int h, int lane, int split,
    const float* kT, const float* vT)
{
    const float SCALE = 0.35355339059327373f;
    float4 qa[G], qb[G];
    int uu[G]; bool val[G];
    #pragma unroll
    for (int g = 0; g < G; g++) {
        int u = u0 + g*8;
        val[g] = (u < UU);
        uu[g] = val[g] ? u : 0;
        int qi = g_top[bh*UU + uu[g]];
        const float4* qp = reinterpret_cast<const float4*>(g_q + (b*LL + qi)*64 + h*8);
        qa[g] = qp[0]; qb[g] = qp[1];
    }
    float ssum[G];
    float pv[G][8];
    #pragma unroll
    for (int g = 0; g < G; g++) {
        ssum[g] = 0.f;
        #pragma unroll
        for (int e = 0; e < 8; e++) pv[g][e] = 0.f;
    }
    for (int j = lane; j < CHUNK; j += 32) {
        float k0 = kT[j],        k1 = kT[520+j],   k2 = kT[2*520+j], k3 = kT[3*520+j];
        float k4 = kT[4*520+j],  k5 = kT[5*520+j], k6 = kT[6*520+j], k7 = kT[7*520+j];
        float v0 = vT[j],        v1 = vT[520+j],   v2 = vT[2*520+j], v3 = vT[3*520+j];
        float v4 = vT[4*520+j],  v5 = vT[5*520+j], v6 = vT[6*520+j], v7 = vT[7*520+j];
        #pragma unroll
        for (int g = 0; g < G; g++) {
            float s = qa[g].x*k0;
            s = fmaf(qa[g].y, k1, s);
            s = fmaf(qa[g].z, k2, s);
            s = fmaf(qa[g].w, k3, s);
            s = fmaf(qb[g].x, k4, s);
            s = fmaf(qb[g].y, k5, s);
            s = fmaf(qb[g].z, k6, s);
            s = fmaf(qb[g].w, k7, s);
            float p = __expf(s * SCALE);
            ssum[g] += p;
            pv[g][0] = fmaf(p, v0, pv[g][0]);
            pv[g][1] = fmaf(p, v1, pv[g][1]);
            pv[g][2] = fmaf(p, v2, pv[g][2]);
            pv[g][3] = fmaf(p, v3, pv[g][3]);
            pv[g][4] = fmaf(p, v4, pv[g][4]);
            pv[g][5] = fmaf(p, v5, pv[g][5]);
            pv[g][6] = fmaf(p, v6, pv[g][6]);
            pv[g][7] = fmaf(p, v7, pv[g][7]);
        }
    }
    #pragma unroll
    for (int g = 0; g < G; g++) {
        #pragma unroll
        for (int o = 16; o; o >>= 1) {
            ssum[g] += __shfl_xor_sync(0xffffffffu, ssum[g], o);
            #pragma unroll
            for (int e = 0; e < 8; e++) pv[g][e] += __shfl_xor_sync(0xffffffffu, pv[g][e], o);
        }
        if (lane == 0 && val[g]) {
            float* pp = g_part + ((bh*UU + uu[g])*NSPLIT + split)*10;
            #pragma unroll
            for (int e = 0; e < 8; e++) pp[e] = pv[g][e];
            pp[8] = ssum[g];
        }
    }
}

__global__ __launch_bounds__(256) void k_attn()
{
    __shared__ float kT[8*520];
    __shared__ float vT[8*520];
    int bh = blockIdx.x >> 4, split = blockIdx.x & 15;
    int b = bh >> 3, h = bh & 7;
    int l0 = split * CHUNK, tid = threadIdx.x;
    for (int i = tid; i < CHUNK*8; i += 256) {
        int j = i >> 3, e = i & 7;
        int g = (b*LL + l0 + j)*64 + h*8 + e;
        kT[e*520 + j] = g_k[g];
        vT[e*520 + j] = g_v[g];
    }
    __syncthreads();
    int w = tid >> 5, lane = tid & 31;
    attn_group<4>(w,      bh, b, h, lane, split, kT, vT);
    attn_group<3>(w + 32, bh, b, h, lane, split, kT, vT);
}

__global__ void k_merge()
{
    int gid = blockIdx.x*256 + threadIdx.x;
    int e = gid & 7, rest = gid >> 3;
    int u = rest % UU, bh = rest / UU;
    int b = bh >> 3, h = bh & 7;
    const float* pp = g_part + ((bh*UU + u)*NSPLIT)*10;
    float pv = 0.f, ss = 0.f;
    for (int s = 0; s < NSPLIT; s++) { pv += pp[s*10 + e]; ss += pp[s*10 + 8]; }
    int qi = g_top[bh*UU + u];
    g_ctx[(b*LL + qi)*64 + h*8 + e] = pv / ss;
}

__device__ __forceinline__ void ln_epilogue(float* out65, int row0, int tid,
    const float* __restrict__ lg, const float* __restrict__ lb)
{
    int w = tid >> 5, lane = tid & 31;
    float gg0 = lg[lane], gg1 = lg[lane+32], bb0 = lb[lane], bb1 = lb[lane+32];
    #pragma unroll
    for (int rr = 0; rr < 4; rr++) {
        int r = w*4 + rr;
        float v0 = out65[r*65 + lane], v1 = out65[r*65 + lane + 32];
        float s = v0 + v1;
        #pragma unroll
        for (int o = 16; o; o >>= 1) s += __shfl_xor_sync(0xffffffffu, s, o);
        float mean = s * (1.0f/64.0f);
        float d0 = v0 - mean, d1 = v1 - mean;
        float s2 = d0*d0 + d1*d1;
        #pragma unroll
        for (int o = 16; o; o >>= 1) s2 += __shfl_xor_sync(0xffffffffu, s2, o);
        float inv = rsqrtf(s2 * (1.0f/64.0f) + 1e-5f);
        int go = (row0 + r)*64;
        g_x[go + lane]      = fmaf(d0 * inv, gg0, bb0);
        g_x[go + lane + 32] = fmaf(d1 * inv, gg1, bb1);
    }
}

__global__ __launch_bounds__(256) void k_wo_ln(
    const float* __restrict__ W, const float* __restrict__ bo,
    const float* __restrict__ lg, const float* __restrict__ lb)
{
    __shared__ __align__(16) float xT[64*36];
    __shared__ float out[32*65];
    int row0 = blockIdx.x * 32, tid = threadIdx.x;
    for (int i = tid; i < 2048; i += 256) { int c=i&63, r=i>>6; xT[c*36+r] = g_ctx[(row0+r)*64+c]; }
    __syncthreads();
    int col = tid & 63, rg = tid >> 6;
    u64 acc2[4];
    #pragma unroll
    for (int p = 0; p < 4; p++) acc2[p] = 0ull;
    #pragma unroll 4
    for (int kk = 0; kk < 64; kk++) {
        float wvv = W[kk*64+col];
        u64 w2 = pk2(wvv, wvv);
        const u64* xp = reinterpret_cast<const u64*>(&xT[kk*36 + rg*8]);
        #pragma unroll
        for (int p = 0; p < 4; p++) fma2(acc2[p], xp[p], w2);
    }
    float bv2 = bo[col];
    #pragma unroll
    for (int p = 0; p < 4; p++) {
        float f0, f1;
        upk2(acc2[p], f0, f1);
        int r = rg*8 + 2*p;
        out[r*65 + col]     = f0 + bv2 + g_x[(row0 + r)*64 + col];
        out[(r+1)*65 + col] = f1 + bv2 + g_x[(row0 + r + 1)*64 + col];
    }
    __syncthreads();
    ln_epilogue(out, row0, tid, lg, lb);
}

// Fused FFN with packed f32x2 math
__global__ __launch_bounds__(256) void k_ffn(
    const float* __restrict__ W1, const float* __restrict__ b1,
    const float* __restrict__ W2, const float* __restrict__ b2,
    const float* __restrict__ lg, const float* __restrict__ lb)
{
    __shared__ __align__(16) float yT[256*36];
    __shared__ __align__(16) float xTo[64*36];
    int row0 = blockIdx.x * 32, tid = threadIdx.x;
    for (int i = tid; i < 2048; i += 256) { int c=i&63, r=i>>6; xTo[c*36+r] = g_x[(row0+r)*64+c]; }
    __syncthreads();
    int col = tid & 63, rg = tid >> 6;
    u64 acc2[16];
    #pragma unroll
    for (int i = 0; i < 16; i++) acc2[i] = 0ull;
    #pragma unroll 2
    for (int kk = 0; kk < 64; kk++) {
        u64 w0 = pk2(W1[kk*256 + col],       W1[kk*256 + col]);
        u64 w1 = pk2(W1[kk*256 + 64 + col],  W1[kk*256 + 64 + col]);
        u64 w2 = pk2(W1[kk*256 + 128 + col], W1[kk*256 + 128 + col]);
        u64 w3 = pk2(W1[kk*256 + 192 + col], W1[kk*256 + 192 + col]);
        const u64* xp = reinterpret_cast<const u64*>(&xTo[kk*36 + rg*8]);
        #pragma unroll
        for (int p = 0; p < 4; p++) {
            u64 xv = xp[p];
            fma2(acc2[p],    xv, w0);
            fma2(acc2[4+p],  xv, w1);
            fma2(acc2[8+p],  xv, w2);
            fma2(acc2[12+p], xv, w3);
        }
    }
    __syncthreads();   // xTo reads done (reused below)
    #pragma unroll
    for (int t = 0; t < 4; t++) {
        float bb = b1[t*64 + col];
        float f[8];
        #pragma unroll
        for (int p = 0; p < 4; p++) {
            float a, c;
            upk2(acc2[t*4+p], a, c);
            f[2*p]   = fmaxf(a + bb, 0.f);
            f[2*p+1] = fmaxf(c + bb, 0.f);
        }
        float4 f0 = {f[0], f[1], f[2], f[3]};
        float4 f1 = {f[4], f[5], f[6], f[7]};
        *reinterpret_cast<float4*>(&yT[(t*64+col)*36 + rg*8])     = f0;
        *reinterpret_cast<float4*>(&yT[(t*64+col)*36 + rg*8 + 4]) = f1;
    }
    __syncthreads();
    u64 a2[4];
    #pragma unroll
    for (int p = 0; p < 4; p++) a2[p] = 0ull;
    #pragma unroll 4
    for (int kk = 0; kk < 256; kk++) {
        float wvv = W2[kk*64 + col];
        u64 w2 = pk2(wvv, wvv);
        const u64* yp = reinterpret_cast<const u64*>(&yT[kk*36 + rg*8]);
        #pragma unroll
        for (int p = 0; p < 4; p++) fma2(a2[p], yp[p], w2);
    }
    float bv2 = b2[col];
    float* out = xTo;
    #pragma unroll
    for (int p = 0; p < 4; p++) {
        float f0, f1;
        upk2(a2[p], f0, f1);
        int r = rg*8 + 2*p;
        out[r*65 + col]     = f0 + bv2 + g_x[(row0 + r)*64 + col];
        out[(r+1)*65 + col] = f1 + bv2 + g_x[(row0 + r + 1)*64 + col];
    }
    __syncthreads();
    ln_epilogue(out, row0, tid, lg, lb);
}

__global__ __launch_bounds__(256) void k_final(
    const float* __restrict__ lg, const float* __restrict__ lb,
    const float* __restrict__ pw, const float* __restrict__ pb,
    float* __restrict__ outp)
{
    int row = blockIdx.x*8 + (threadIdx.x >> 5);
    int lane = threadIdx.x & 31;
    const float* xr = g_x + row*64;
    float v0 = xr[lane], v1 = xr[lane+32];
    float s = v0 + v1;
    #pragma unroll
    for (int o = 16; o; o >>= 1) s += __shfl_xor_sync(0xffffffffu, s, o);
    float mean = s * (1.0f/64.0f);
    float d0 = v0 - mean, d1 = v1 - mean;
    float s2 = d0*d0 + d1*d1;
    #pragma unroll
    for (int o = 16; o; o >>= 1) s2 += __shfl_xor_sync(0xffffffffu, s2, o);
    float inv = rsqrtf(s2 * (1.0f/64.0f) + 1e-5f);
    float xn0 = fmaf(d0 * inv, lg[lane],    lb[lane]);
    float xn1 = fmaf(d1 * inv, lg[lane+32], lb[lane+32]);
    float lgt[5];
    #pragma unroll
    for (int c = 0; c < 5; c++) {
        float t = fmaf(xn0, pw[lane*5 + c], xn1 * pw[(lane+32)*5 + c]);
        #pragma unroll
        for (int o = 16; o; o >>= 1) t += __shfl_xor_sync(0xffffffffu, t, o);
        lgt[c] = t + pb[c];
    }
    float m = lgt[0];
    #pragma unroll
    for (int c = 1; c < 5; c++) m = fmaxf(m, lgt[c]);
    float e[5], se = 0.f;
    #pragma unroll
    for (int c = 0; c < 5; c++) { e[c] = __expf(lgt[c] - m); se += e[c]; }
    float rse = 1.0f / se;
    if (lane == 0) {
        #pragma unroll
        for (int c = 0; c < 5; c++) outp[row*5 + c] = e[c] * rse;
    }
}

extern "C" void kernel_launch(void* const* d_in, const int* in_sizes, int n_in,
                              void* d_out, int out_size)
{
    const float* x_enc   = (const float*)d_in[0];
    const int*   idxs    = (const int*)  d_in[1];
    const float* emb_w   = (const float*)d_in[2];
    const float* Wq      = (const float*)d_in[3];
    const float* bq      = (const float*)d_in[4];
    const float* Wk      = (const float*)d_in[5];
    const float* bk      = (const float*)d_in[6];
    const float* Wv      = (const float*)d_in[7];
    const float* bv      = (const float*)d_in[8];
    const float* Wo      = (const float*)d_in[9];
    const float* bo      = (const float*)d_in[10];
    const float* c1w     = (const float*)d_in[11];
    const float* c1b     = (const float*)d_in[12];
    const float* c2w     = (const float*)d_in[13];
    const float* c2b     = (const float*)d_in[14];
    const float* ln1g    = (const float*)d_in[15];
    const float* ln1b    = (const float*)d_in[16];
    const float* ln2g    = (const float*)d_in[17];
    const float* ln2b    = (const float*)d_in[18];
    const float* lnfg    = (const float*)d_in[19];
    const float* lnfb    = (const float*)d_in[20];
    const float* projw   = (const float*)d_in[21];
    const float* projb   = (const float*)d_in[22];
    float* outp = (float*)d_out;

    k_div<<<1, 32>>>();
    k_embed<<<ROWS*DM/256, 256>>>(x_enc, emb_w);

    for (int i = 0; i < 2; i++) {
        k_qkv<<<ROWS/32, 256>>>(Wq + i*DM*DM, bq + i*DM, Wk + i*DM*DM, bk + i*DM,
                                Wv + i*DM*DM, bv + i*DM);
        k_mscore<<<ROWS/8, 256>>>(idxs + i*LL*UU);
        k_topk<<<BB*HH, 256>>>();
        k_vpart<<<BB*16, 256>>>();
        k_vmerge<<<1, BB*DM>>>();
        k_ctxfill<<<ROWS*DM/256, 256>>>();
        k_attn<<<BB*HH*NSPLIT, 256>>>();
        k_merge<<<BB*HH*UU*8/256, 256>>>();
        k_wo_ln<<<ROWS/32, 256>>>(Wo + i*DM*DM, bo + i*DM, ln1g + i*DM, ln1b + i*DM);
        k_ffn<<<ROWS/32, 256>>>(c1w + i*DM*DFF, c1b + i*DFF, c2w + i*DFF*DM, c2b + i*DM,
                                ln2g + i*DM, ln2b + i*DM);
    }
    k_final<<<ROWS/8, 256>>>(lnfg, lnfb, projw, projb, outp);
}